// round 6
// baseline (speedup 1.0000x reference)
#include <cuda_runtime.h>

#define NN 50000
#define FEAT 64
#define HID 128
#define NE 640000

// Scratch (allocation-free per harness rules)
__device__ float g_deg[NN];
__device__ float g_agg[NN * 128];
__device__ float g_h[NN * 128];

__global__ void zero_kernel(float4* __restrict__ p, int n4) {
    int i = blockIdx.x * blockDim.x + threadIdx.x;
    int st = gridDim.x * blockDim.x;
    float4 z = make_float4(0.f, 0.f, 0.f, 0.f);
    for (; i < n4; i += st) p[i] = z;
}

// Per-edge gather + vector atomic scatter. Thread handles one float4 chunk of one edge.
template <int K, bool DO_DEG>
__global__ void scatter_kernel(const int* __restrict__ src, const int* __restrict__ dst,
                               const float* __restrict__ x, float* __restrict__ agg,
                               float* __restrict__ deg) {
    const int C = K / 4;
    const int total = NE * C;
    int i = blockIdx.x * blockDim.x + threadIdx.x;
    int st = gridDim.x * blockDim.x;
    for (; i < total; i += st) {
        int e = i / C;          // C is power of 2 -> shift
        int c = i - e * C;
        int s = __ldg(src + e);
        int d = __ldg(dst + e);
        float4 v = __ldg((const float4*)x + (size_t)s * C + c);
        float* a = agg + (size_t)d * K + c * 4;
        asm volatile("red.global.add.v4.f32 [%0], {%1,%2,%3,%4};"
                     :: "l"(a), "f"(v.x), "f"(v.y), "f"(v.z), "f"(v.w)
                     : "memory");
        if (DO_DEG && c == 0) atomicAdd(deg + d, 1.0f);
    }
}

// out[n, j] = (RELU?) b[j] + sum_k Wl[j,k]*mean[n,k] + Wr[j,k]*x[n,k]
// Block = 256 threads. Warp w handles 4 nodes; lanes cover 128 outputs (4 each).
// W kept transposed in SMEM: Ws[k][j] -> float4 across j, conflict-free.
template <int K, bool RELU>
__global__ void layer_kernel(const float* __restrict__ Wl, const float* __restrict__ bl,
                             const float* __restrict__ Wr,
                             const float* __restrict__ xin,   // [NN, K]
                             const float* __restrict__ agg,   // [NN, K]
                             const float* __restrict__ deg,   // [NN]
                             float* __restrict__ out) {       // [NN, 128]
    extern __shared__ float sm[];
    float* Wsl = sm;                    // K*128
    float* Wsr = Wsl + K * 128;         // K*128
    float* xs  = Wsr + K * 128;         // 32 nodes * 2K  (mean | x)
    float* bs  = xs + 32 * 2 * K;       // 128

    const int tid = threadIdx.x;

    // Load W transposed (one-time per block)
    for (int i = tid; i < 128 * K; i += 256) {
        int j = i / K;
        int k = i - j * K;
        Wsl[k * 128 + j] = Wl[i];
        Wsr[k * 128 + j] = Wr[i];
    }
    if (tid < 128) bs[tid] = bl[tid];

    const int jg = (tid & 31) * 4;   // output base (lane -> 4 consecutive outputs)
    const int ns = tid >> 5;         // warp id -> node group (4 nodes)
    const int F4 = K / 4;

    for (int base = blockIdx.x * 32; base < NN; base += gridDim.x * 32) {
        __syncthreads();   // protect xs from previous-iteration readers / cover W load

        // Stage mean and x for up to 32 nodes into SMEM
        int nNodes = min(32, NN - base);
        for (int i = tid; i < nNodes * (K / 2); i += 256) {
            int nl = i / (K / 2);
            int q  = i - nl * (K / 2);
            int node = base + nl;
            if (q < F4) {
                float4 v = __ldg((const float4*)agg + (size_t)node * F4 + q);
                float inv = 1.0f / fmaxf(__ldg(deg + node), 1.0f);
                v.x *= inv; v.y *= inv; v.z *= inv; v.w *= inv;
                ((float4*)(xs + nl * 2 * K))[q] = v;
            } else {
                float4 v = __ldg((const float4*)xin + (size_t)node * F4 + (q - F4));
                ((float4*)(xs + nl * 2 * K))[q] = v;
            }
        }
        __syncthreads();

        float acc[4][4];
#pragma unroll
        for (int nb = 0; nb < 4; nb++) {
            acc[nb][0] = bs[jg + 0];
            acc[nb][1] = bs[jg + 1];
            acc[nb][2] = bs[jg + 2];
            acc[nb][3] = bs[jg + 3];
        }

        const float* xp0 = xs + (ns * 4 + 0) * 2 * K;
        const float* xp1 = xs + (ns * 4 + 1) * 2 * K;
        const float* xp2 = xs + (ns * 4 + 2) * 2 * K;
        const float* xp3 = xs + (ns * 4 + 3) * 2 * K;

        for (int k = 0; k < K; k += 4) {
            float4 xm[4], xe[4];
            xm[0] = *(const float4*)(xp0 + k);  xe[0] = *(const float4*)(xp0 + K + k);
            xm[1] = *(const float4*)(xp1 + k);  xe[1] = *(const float4*)(xp1 + K + k);
            xm[2] = *(const float4*)(xp2 + k);  xe[2] = *(const float4*)(xp2 + K + k);
            xm[3] = *(const float4*)(xp3 + k);  xe[3] = *(const float4*)(xp3 + K + k);
#pragma unroll
            for (int kk = 0; kk < 4; kk++) {
                float4 wl = *(const float4*)(Wsl + (k + kk) * 128 + jg);
                float4 wr = *(const float4*)(Wsr + (k + kk) * 128 + jg);
#pragma unroll
                for (int nb = 0; nb < 4; nb++) {
                    float m = reinterpret_cast<const float*>(&xm[nb])[kk];
                    float e = reinterpret_cast<const float*>(&xe[nb])[kk];
                    acc[nb][0] = fmaf(wl.x, m, fmaf(wr.x, e, acc[nb][0]));
                    acc[nb][1] = fmaf(wl.y, m, fmaf(wr.y, e, acc[nb][1]));
                    acc[nb][2] = fmaf(wl.z, m, fmaf(wr.z, e, acc[nb][2]));
                    acc[nb][3] = fmaf(wl.w, m, fmaf(wr.w, e, acc[nb][3]));
                }
            }
        }

#pragma unroll
        for (int nb = 0; nb < 4; nb++) {
            int node = base + ns * 4 + nb;
            if (node < NN) {
                float4 o;
                if (RELU) {
                    o.x = fmaxf(acc[nb][0], 0.f);
                    o.y = fmaxf(acc[nb][1], 0.f);
                    o.z = fmaxf(acc[nb][2], 0.f);
                    o.w = fmaxf(acc[nb][3], 0.f);
                } else {
                    o.x = acc[nb][0]; o.y = acc[nb][1];
                    o.z = acc[nb][2]; o.w = acc[nb][3];
                }
                *(float4*)(out + (size_t)node * 128 + jg) = o;
            }
        }
    }
}

static const int SMEM1 = (64 * 128 * 2 + 32 * 2 * 64 + 128) * (int)sizeof(float);   // 82432
static const int SMEM2 = (128 * 128 * 2 + 32 * 2 * 128 + 128) * (int)sizeof(float); // 164352

extern "C" void kernel_launch(void* const* d_in, const int* in_sizes, int n_in,
                              void* d_out, int out_size) {
    const int*   edge = (const int*)d_in[0];
    const float* emb  = (const float*)d_in[1];
    const float* W1l  = (const float*)d_in[2];
    const float* b1l  = (const float*)d_in[3];
    const float* W1r  = (const float*)d_in[4];
    const float* W2l  = (const float*)d_in[5];
    const float* b2l  = (const float*)d_in[6];
    const float* W2r  = (const float*)d_in[7];
    float* out = (float*)d_out;

    const int* src = edge;
    const int* dst = edge + NE;

    float *agg, *deg, *h;
    cudaGetSymbolAddress((void**)&agg, g_agg);
    cudaGetSymbolAddress((void**)&deg, g_deg);
    cudaGetSymbolAddress((void**)&h,   g_h);

    cudaFuncSetAttribute(layer_kernel<64, true>,
                         cudaFuncAttributeMaxDynamicSharedMemorySize, SMEM1);
    cudaFuncSetAttribute(layer_kernel<128, false>,
                         cudaFuncAttributeMaxDynamicSharedMemorySize, SMEM2);

    // Layer 1
    zero_kernel<<<1024, 256>>>((float4*)agg, NN * 128 / 4);
    zero_kernel<<<64, 256>>>((float4*)deg, NN / 4);
    scatter_kernel<64, true><<<2368, 256>>>(src, dst, emb, agg, deg);
    layer_kernel<64, true><<<296, 256, SMEM1>>>(W1l, b1l, W1r, emb, agg, deg, h);

    // Layer 2
    zero_kernel<<<1024, 256>>>((float4*)agg, NN * 128 / 4);
    scatter_kernel<128, false><<<2368, 256>>>(src, dst, h, agg, deg);
    layer_kernel<128, false><<<148, 256, SMEM2>>>(W2l, b2l, W2r, h, agg, deg, out);
}